// round 11
// baseline (speedup 1.0000x reference)
#include <cuda_runtime.h>
#include <cuda_bf16.h>
#include <cstdint>
#include <cstddef>

#define N_NODES 50000
#define FEAT 128
#define E_MAX 800000
#define WSTRIDE 136   // bf16 elements per row in smem (272B = 17 * 16B -> conflict-free ldmatrix)

// ---------------- scratch (static device globals; no allocs) ----------------
__device__ __align__(16) unsigned char g_needed[N_NODES];
__device__ int                         g_cnt[N_NODES];
__device__ __align__(16) float         g_accT[(size_t)N_NODES * FEAT];
__device__ __align__(16) float         g_T[(size_t)N_NODES * FEAT];
__device__ int                         g_is64;
__device__ int                         g_nact;
__device__ __align__(8)  int2          g_ec[E_MAX];    // compacted edges

__device__ __forceinline__ uint32_t smem_u32(const void* p) {
    uint32_t a;
    asm("{ .reg .u64 t; cvta.to.shared.u64 t, %1; cvt.u32.u64 %0, t; }" : "=r"(a) : "l"(p));
    return a;
}

#define LDSM4(r, addr) \
    asm volatile("ldmatrix.sync.aligned.m8n8.x4.shared.b16 {%0,%1,%2,%3}, [%4];" \
        : "=r"((r)[0]), "=r"((r)[1]), "=r"((r)[2]), "=r"((r)[3]) : "r"(addr))

#define MMA16816(d, a, b0, b1) \
    asm volatile("mma.sync.aligned.m16n8k16.row.col.f32.bf16.bf16.f32 " \
        "{%0,%1,%2,%3}, {%4,%5,%6,%7}, {%8,%9}, {%0,%1,%2,%3};" \
        : "+f"((d)[0]), "+f"((d)[1]), "+f"((d)[2]), "+f"((d)[3]) \
        : "r"((a)[0]), "r"((a)[1]), "r"((a)[2]), "r"((a)[3]), "r"(b0), "r"(b1))

// ---------------------------------------------------------------------------
// Probe index dtype; also zero g_nact for this call.
// ---------------------------------------------------------------------------
__global__ void probe_kernel(const int* __restrict__ e, int nwords)
{
    int lane = threadIdx.x;
    int n = nwords < 2048 ? nwords : 2048;
    int any = 0;
    for (int i = 1 + 2 * lane; i < n; i += 64) any |= e[i];
    #pragma unroll
    for (int o = 16; o; o >>= 1) any |= __shfl_xor_sync(0xffffffffu, any, o);
    if (lane == 0) { g_is64 = (any == 0) ? 1 : 0; g_nact = 0; }
}

// ---------------------------------------------------------------------------
// Mark needed nodes + zero their cnt and accT row (one warp per node_idx).
// ---------------------------------------------------------------------------
__global__ __launch_bounds__(256)
void mark_zero_kernel(const void* __restrict__ node_idx, int B)
{
    int w    = (blockIdx.x * blockDim.x + threadIdx.x) >> 5;
    int lane = threadIdx.x & 31;
    if (w >= B) return;
    long long s = g_is64 ? ((const long long*)node_idx)[w]
                         : (long long)((const int*)node_idx)[w];
    if ((unsigned long long)s >= (unsigned long long)N_NODES) return;
    if (lane == 0) { g_needed[s] = 1; g_cnt[s] = 0; }
    *(float4*)&g_accT[(size_t)s * FEAT + lane * 4] = make_float4(0.f, 0.f, 0.f, 0.f);
}

// ---------------------------------------------------------------------------
// Filter + compact edges; count degrees for needed src.
// ---------------------------------------------------------------------------
__global__ __launch_bounds__(256)
void filter_kernel(const void* __restrict__ edges, const int* __restrict__ ind_ptr, int E)
{
    int i    = blockIdx.x * blockDim.x + threadIdx.x;
    int lane = threadIdx.x & 31;
    int is64 = g_is64;
    int keep_self = (*ind_ptr < 2);

    int src = 0, dst = 0;
    bool act = false;
    if (i < E) {
        if (is64) { longlong2 p = ((const longlong2*)edges)[i]; src = (int)p.x; dst = (int)p.y; }
        else      { int2 p = ((const int2*)edges)[i];           src = p.x;      dst = p.y; }
        act = ((src != dst) | keep_self)
              && ((unsigned)src < (unsigned)N_NODES)
              && ((unsigned)dst < (unsigned)N_NODES)
              && g_needed[src];
    }
    unsigned m = __ballot_sync(0xffffffffu, act);
    int cnt = __popc(m);
    int base = 0;
    if (lane == 0 && cnt) base = atomicAdd(&g_nact, cnt);
    base = __shfl_sync(0xffffffffu, base, 0);
    if (act) {
        int off = __popc(m & ((1u << lane) - 1u));
        g_ec[base + off] = make_int2(src, dst);
        atomicAdd(&g_cnt[src], 1);
    }
}

// ---------------------------------------------------------------------------
// GEMM1 via mma.sync (HMMA bf16, 3-pass split): T = tanh(X @ W1 + b1).
// CTA: 256 threads / 8 warps; tile 64 rows x 128 cols; K=128 in smem.
// smem = 104448B -> 2 CTAs/SM (16 warps/SM) for latency hiding.
// Warp w: rows (w&3)*16 .. +15, cols (w>>2)*64 .. +63.
// W1 converted/split in-kernel from global (L2-resident; no prep pass).
// ---------------------------------------------------------------------------
#define SM_XHI 0
#define SM_XLO (SM_XHI + 64 * WSTRIDE * 2)
#define SM_WHI (SM_XLO + 64 * WSTRIDE * 2)
#define SM_WLO (SM_WHI + 128 * WSTRIDE * 2)
#define SM_TOT (SM_WLO + 128 * WSTRIDE * 2)

__global__ __launch_bounds__(256, 2)
void gemm1_mma_kernel(const float* __restrict__ X,
                      const float* __restrict__ W1,
                      const float* __restrict__ b1,
                      int Nrows)
{
    extern __shared__ char smem[];
    uint32_t sb  = smem_u32(smem);
    int tid  = threadIdx.x;
    int wid  = tid >> 5;
    int lane = tid & 31;
    int row0 = blockIdx.x * 64;

    // --- convert W1 [k][n] fp32 -> split bf16 [n][WSTRIDE] k-major in smem ---
    {
        unsigned short* sWhi = (unsigned short*)(smem + SM_WHI);
        unsigned short* sWlo = (unsigned short*)(smem + SM_WLO);
        #pragma unroll 8
        for (int i = 0; i < 64; i++) {
            int idx = i * 256 + tid;          // coalesced over n
            int k = idx >> 7, n = idx & 127;
            float w = W1[idx];
            __nv_bfloat16 hi = __float2bfloat16(w);
            __nv_bfloat16 lo = __float2bfloat16(w - __bfloat162float(hi));
            unsigned short hs, ls;
            *(__nv_bfloat16*)&hs = hi;
            *(__nv_bfloat16*)&ls = lo;
            sWhi[n * WSTRIDE + k] = hs;
            sWlo[n * WSTRIDE + k] = ls;
        }
    }

    // --- convert X tile (64 rows) fp32 -> bf16 hi/lo, padded [row][WSTRIDE] ---
    {
        int r  = tid >> 2;            // 0..63
        int q  = tid & 3;             // 32-col quarter
        int gr = row0 + r;
        const float* xr = X + (size_t)gr * FEAT;
        #pragma unroll
        for (int j = 0; j < 4; j++) {
            int c0 = q * 32 + j * 8;
            float4 v0 = make_float4(0.f, 0.f, 0.f, 0.f), v1 = v0;
            if (gr < Nrows) {
                v0 = *(const float4*)&xr[c0];
                v1 = *(const float4*)&xr[c0 + 4];
            }
            float xs[8] = {v0.x, v0.y, v0.z, v0.w, v1.x, v1.y, v1.z, v1.w};
            unsigned hi[4], lo[4];
            #pragma unroll
            for (int p = 0; p < 4; p++) {
                float a = xs[2 * p], b = xs[2 * p + 1];
                __nv_bfloat162 h = __floats2bfloat162_rn(a, b);
                float2 hf = __bfloat1622float2(h);
                __nv_bfloat162 l = __floats2bfloat162_rn(a - hf.x, b - hf.y);
                hi[p] = *(unsigned*)&h;
                lo[p] = *(unsigned*)&l;
            }
            int off = (r * WSTRIDE + c0) * 2;
            *(uint4*)(smem + SM_XHI + off) = make_uint4(hi[0], hi[1], hi[2], hi[3]);
            *(uint4*)(smem + SM_XLO + off) = make_uint4(lo[0], lo[1], lo[2], lo[3]);
        }
    }
    __syncthreads();

    // --- fragment address bases ---
    int sub = lane >> 3, rr = lane & 7;
    int wr = (wid & 3) * 16;          // warp row base
    int wc = (wid >> 2) * 64;         // warp col base
    int a_m = wr + (sub & 1) * 8 + rr;
    int a_k = (sub >> 1) * 8;
    uint32_t aOff = (uint32_t)((a_m * WSTRIDE + a_k) * 2);
    int b_n = wc + (sub >> 1) * 8 + rr;
    int b_k = (sub & 1) * 8;
    uint32_t bOff = (uint32_t)((b_n * WSTRIDE + b_k) * 2);

    float d[8][4];
    #pragma unroll
    for (int j = 0; j < 8; j++)
        #pragma unroll
        for (int q = 0; q < 4; q++) d[j][q] = 0.f;

    #pragma unroll 1
    for (int pass = 0; pass < 3; pass++) {
        uint32_t aBase = sb + ((pass < 2)  ? SM_XHI : SM_XLO) + aOff;
        uint32_t bBase = sb + ((pass == 1) ? SM_WLO : SM_WHI) + bOff;
        #pragma unroll 2
        for (int ks = 0; ks < 8; ks++) {
            uint32_t a[4];
            LDSM4(a, aBase + (uint32_t)ks * 32);
            uint32_t bAddr = bBase + (uint32_t)ks * 32;
            #pragma unroll
            for (int np = 0; np < 4; np++) {
                uint32_t b[4];
                LDSM4(b, bAddr + (uint32_t)(np * 16 * WSTRIDE * 2));
                MMA16816(d[np * 2],     a, b[0], b[1]);
                MMA16816(d[np * 2 + 1], a, b[2], b[3]);
            }
        }
    }

    // --- epilogue: bias + tanh, store to g_T ---
    {
        int g = lane >> 2, c = lane & 3;
        int gr0 = row0 + wr + g, gr1 = gr0 + 8;
        #pragma unroll
        for (int j = 0; j < 8; j++) {
            int col = wc + j * 8 + c * 2;
            float bx = b1[col], by = b1[col + 1];
            if (gr0 < Nrows) {
                float2 o;
                o.x = tanhf(d[j][0] + bx);
                o.y = tanhf(d[j][1] + by);
                *(float2*)&g_T[(size_t)gr0 * FEAT + col] = o;
            }
            if (gr1 < Nrows) {
                float2 o;
                o.x = tanhf(d[j][2] + bx);
                o.y = tanhf(d[j][3] + by);
                *(float2*)&g_T[(size_t)gr1 * FEAT + col] = o;
            }
        }
    }
}

// ---------------------------------------------------------------------------
// Aggregate compacted edges: one warp per edge; lane handles 4 floats.
// ---------------------------------------------------------------------------
__global__ __launch_bounds__(256)
void agg_kernel()
{
    int gw   = (blockIdx.x * blockDim.x + threadIdx.x) >> 5;
    int lane = threadIdx.x & 31;
    int nw   = (gridDim.x * blockDim.x) >> 5;
    int nact = g_nact;

    for (int i = gw; i < nact; i += nw) {
        int2 e = g_ec[i];
        float4 hv = *(const float4*)&g_T[(size_t)e.y * FEAT + lane * 4];
        float* dp = &g_accT[(size_t)e.x * FEAT + lane * 4];
        asm volatile("red.global.add.v4.f32 [%0], {%1,%2,%3,%4};"
                     :: "l"(dp), "f"(hv.x), "f"(hv.y), "f"(hv.z), "f"(hv.w)
                     : "memory");
    }
}

// ---------------------------------------------------------------------------
// GEMM2 (B rows only): out[i] = flag_i * ((accT[s_i]/cnt_i) @ W2 + b2).
// ---------------------------------------------------------------------------
__global__ __launch_bounds__(256)
void gemm2_kernel(const void* __restrict__ node_idx,
                  const float* __restrict__ W2,
                  const float* __restrict__ b2,
                  float* __restrict__ out,
                  int B)
{
    extern __shared__ float sm[];
    float* sW    = sm;
    float* sA    = sm + 16384;
    float* sFlag = sm + 16384 + 8192;

    int tid  = threadIdx.x;
    int i0   = blockIdx.x * 64;
    int is64 = g_is64;

    for (int i = tid * 4; i < 16384; i += 256 * 4)
        *(float4*)&sW[i] = *(const float4*)&W2[i];

    {
        int r = tid >> 2;
        int q = tid & 3;
        int i = i0 + r;
        float  scale = 0.f;
        size_t s = 0;
        int    c = 0;
        bool   valid = (i < B);
        if (valid) {
            long long sv = is64 ? ((const long long*)node_idx)[i]
                                : (long long)((const int*)node_idx)[i];
            if ((unsigned long long)sv < (unsigned long long)N_NODES) {
                s = (size_t)sv;
                c = g_cnt[s];
            } else valid = false;
            scale = (c > 0) ? (1.f / (float)c) : 0.f;
        }
        if (q == 0) sFlag[r] = (valid && c > 0) ? 1.f : 0.f;
        #pragma unroll
        for (int j = 0; j < 8; j++) {
            int col = q * 32 + j * 4;
            float4 v = make_float4(0.f, 0.f, 0.f, 0.f);
            if (valid) {
                v = *(const float4*)&g_accT[s * FEAT + col];
                v.x *= scale; v.y *= scale; v.z *= scale; v.w *= scale;
            }
            *(float4*)&sA[r * 128 + col] = v;
        }
    }
    __syncthreads();

    int tr = tid >> 5;
    int tc = tid & 31;

    float acc[8][4];
    #pragma unroll
    for (int r = 0; r < 8; r++)
        #pragma unroll
        for (int c = 0; c < 4; c++) acc[r][c] = 0.f;

    #pragma unroll 4
    for (int k = 0; k < 128; k += 4) {
        float4 p0 = *(const float4*)&sW[(k + 0) * 128 + tc * 4];
        float4 p1 = *(const float4*)&sW[(k + 1) * 128 + tc * 4];
        float4 p2 = *(const float4*)&sW[(k + 2) * 128 + tc * 4];
        float4 p3 = *(const float4*)&sW[(k + 3) * 128 + tc * 4];
        #pragma unroll
        for (int r = 0; r < 8; r++) {
            float4 a = *(const float4*)&sA[(tr * 8 + r) * 128 + k];
            acc[r][0] += a.x * p0.x + a.y * p1.x + a.z * p2.x + a.w * p3.x;
            acc[r][1] += a.x * p0.y + a.y * p1.y + a.z * p2.y + a.w * p3.y;
            acc[r][2] += a.x * p0.z + a.y * p1.z + a.z * p2.z + a.w * p3.z;
            acc[r][3] += a.x * p0.w + a.y * p1.w + a.z * p2.w + a.w * p3.w;
        }
    }

    float4 bias = *(const float4*)&b2[tc * 4];
    #pragma unroll
    for (int r = 0; r < 8; r++) {
        int rl = tr * 8 + r;
        int i  = i0 + rl;
        if (i < B) {
            float f = sFlag[rl];
            float4 o;
            o.x = f * (acc[r][0] + bias.x);
            o.y = f * (acc[r][1] + bias.y);
            o.z = f * (acc[r][2] + bias.z);
            o.w = f * (acc[r][3] + bias.w);
            *(float4*)&out[(size_t)i * FEAT + tc * 4] = o;
        }
    }
}

// ---------------------------------------------------------------------------
extern "C" void kernel_launch(void* const* d_in, const int* in_sizes, int n_in,
                              void* d_out, int out_size)
{
    const void*  edges    = d_in[0];
    const void*  node_idx = d_in[1];
    const float* X        = (const float*)d_in[2];
    const float* W1       = (const float*)d_in[3];
    const float* b1       = (const float*)d_in[4];
    const float* W2       = (const float*)d_in[5];
    const float* b2       = (const float*)d_in[6];
    const int*   ind      = (const int*)d_in[7];

    int E = in_sizes[0] / 2;
    int B = in_sizes[1];
    int N = in_sizes[2] / FEAT;
    float* out = (float*)d_out;

    void* p_needed;
    cudaGetSymbolAddress(&p_needed, g_needed);
    cudaMemsetAsync(p_needed, 0, N_NODES);

    cudaFuncSetAttribute(gemm1_mma_kernel, cudaFuncAttributeMaxDynamicSharedMemorySize, SM_TOT);
    cudaFuncSetAttribute(gemm2_kernel,     cudaFuncAttributeMaxDynamicSharedMemorySize, 98560);

    probe_kernel<<<1, 32>>>((const int*)edges, in_sizes[0]);
    mark_zero_kernel<<<(B * 32 + 255) / 256, 256>>>(node_idx, B);
    filter_kernel<<<(E + 255) / 256, 256>>>(edges, ind, E);
    gemm1_mma_kernel<<<(N + 63) / 64, 256, SM_TOT>>>(X, W1, b1, N);
    agg_kernel<<<1184, 256>>>();
    gemm2_kernel<<<(B + 63) / 64, 256, 98560>>>(node_idx, W2, b2, out, B);
}

// round 12
// speedup vs baseline: 1.1240x; 1.1240x over previous
#include <cuda_runtime.h>
#include <cuda_bf16.h>
#include <cstdint>
#include <cstddef>

#define N_NODES 50000
#define FEAT 128
#define E_MAX 800000
#define WSTRIDE 136   // bf16 elements per row in smem (272B = 17 * 16B -> conflict-free ldmatrix)

// ---------------- scratch (static device globals; no allocs) ----------------
__device__ __align__(16) unsigned char g_needed[N_NODES];
__device__ int                         g_cnt[N_NODES];
__device__ __align__(16) float         g_accT[(size_t)N_NODES * FEAT];
__device__ __align__(16) float         g_T[(size_t)N_NODES * FEAT];
__device__ int                         g_is64;
__device__ int                         g_nact;
__device__ __align__(8)  int2          g_ec[E_MAX];                 // compacted edges
__device__ __align__(16) unsigned short g_Whi[128 * WSTRIDE];       // W1^T hi, padded [n][k]
__device__ __align__(16) unsigned short g_Wlo[128 * WSTRIDE];       // W1^T lo, padded [n][k]

__device__ __forceinline__ uint32_t smem_u32(const void* p) {
    uint32_t a;
    asm("{ .reg .u64 t; cvta.to.shared.u64 t, %1; cvt.u32.u64 %0, t; }" : "=r"(a) : "l"(p));
    return a;
}

#define LDSM4(r, addr) \
    asm volatile("ldmatrix.sync.aligned.m8n8.x4.shared.b16 {%0,%1,%2,%3}, [%4];" \
        : "=r"((r)[0]), "=r"((r)[1]), "=r"((r)[2]), "=r"((r)[3]) : "r"(addr))

#define MMA16816(d, a, b0, b1) \
    asm volatile("mma.sync.aligned.m16n8k16.row.col.f32.bf16.bf16.f32 " \
        "{%0,%1,%2,%3}, {%4,%5,%6,%7}, {%8,%9}, {%0,%1,%2,%3};" \
        : "+f"((d)[0]), "+f"((d)[1]), "+f"((d)[2]), "+f"((d)[3]) \
        : "r"((a)[0]), "r"((a)[1]), "r"((a)[2]), "r"((a)[3]), "r"(b0), "r"(b1))

// ---------------------------------------------------------------------------
// mark_zero: (a) detect index dtype per-CTA and publish g_is64 / g_nact=0;
// (b) W1 split into bf16 hi/lo padded global images (first 64 CTAs);
// (c) mark needed nodes + zero their cnt and accT row (one warp per node_idx).
// ---------------------------------------------------------------------------
__global__ __launch_bounds__(256)
void mark_zero_kernel(const int* __restrict__ edges_raw,
                      const void* __restrict__ node_idx,
                      const float* __restrict__ W1,
                      int B, int E2)
{
    __shared__ int s64;
    int tid = threadIdx.x;

    // --- per-CTA dtype detect: int64 arrays of idx<2^31 have zero odd words ---
    if (tid < 32) {
        int n = E2 < 2048 ? E2 : 2048;
        int any = 0;
        for (int i = 1 + 2 * tid; i < n; i += 64) any |= edges_raw[i];
        #pragma unroll
        for (int o = 16; o; o >>= 1) any |= __shfl_xor_sync(0xffffffffu, any, o);
        if (tid == 0) s64 = (any == 0) ? 1 : 0;
    }
    __syncthreads();
    int is64 = s64;
    if (blockIdx.x == 0 && tid == 0) { g_is64 = is64; g_nact = 0; }

    // --- W split (piggy-backed; 16384 elements over first 64 CTAs) ---
    {
        int widx = blockIdx.x * 256 + tid;
        if (widx < 16384) {
            int k = widx >> 7, n = widx & 127;       // coalesced W1 read
            float w = W1[widx];
            __nv_bfloat16 hi = __float2bfloat16(w);
            __nv_bfloat16 lo = __float2bfloat16(w - __bfloat162float(hi));
            unsigned short hs, ls;
            *(__nv_bfloat16*)&hs = hi;
            *(__nv_bfloat16*)&ls = lo;
            g_Whi[n * WSTRIDE + k] = hs;
            g_Wlo[n * WSTRIDE + k] = ls;
        }
    }

    // --- mark + zero (one warp per node) ---
    int w    = (blockIdx.x * 256 + tid) >> 5;
    int lane = tid & 31;
    if (w >= B) return;
    long long s = is64 ? ((const long long*)node_idx)[w]
                       : (long long)((const int*)node_idx)[w];
    if ((unsigned long long)s >= (unsigned long long)N_NODES) return;
    if (lane == 0) { g_needed[s] = 1; g_cnt[s] = 0; }
    *(float4*)&g_accT[(size_t)s * FEAT + lane * 4] = make_float4(0.f, 0.f, 0.f, 0.f);
}

// ---------------------------------------------------------------------------
// Filter + compact edges; count degrees for needed src.
// ---------------------------------------------------------------------------
__global__ __launch_bounds__(256)
void filter_kernel(const void* __restrict__ edges, const int* __restrict__ ind_ptr, int E)
{
    int i    = blockIdx.x * blockDim.x + threadIdx.x;
    int lane = threadIdx.x & 31;
    int is64 = g_is64;
    int keep_self = (*ind_ptr < 2);

    int src = 0, dst = 0;
    bool act = false;
    if (i < E) {
        if (is64) { longlong2 p = ((const longlong2*)edges)[i]; src = (int)p.x; dst = (int)p.y; }
        else      { int2 p = ((const int2*)edges)[i];           src = p.x;      dst = p.y; }
        act = ((src != dst) | keep_self)
              && ((unsigned)src < (unsigned)N_NODES)
              && ((unsigned)dst < (unsigned)N_NODES)
              && g_needed[src];
    }
    unsigned m = __ballot_sync(0xffffffffu, act);
    int cnt = __popc(m);
    int base = 0;
    if (lane == 0 && cnt) base = atomicAdd(&g_nact, cnt);
    base = __shfl_sync(0xffffffffu, base, 0);
    if (act) {
        int off = __popc(m & ((1u << lane) - 1u));
        g_ec[base + off] = make_int2(src, dst);
        atomicAdd(&g_cnt[src], 1);
    }
}

// ---------------------------------------------------------------------------
// GEMM1 via mma.sync (HMMA bf16, 3-pass split): T = tanh(X @ W1 + b1).
// CTA: 256 threads / 8 warps; tile 64 rows x 128 cols; K=128 in smem.
// smem = 104448B -> 2 CTAs/SM. W copied linearly from pre-split global images
// (conflict-free); X-convert STS remapped for conflict-free banks.
// ---------------------------------------------------------------------------
#define SM_XHI 0
#define SM_XLO (SM_XHI + 64 * WSTRIDE * 2)
#define SM_WHI (SM_XLO + 64 * WSTRIDE * 2)
#define SM_WLO (SM_WHI + 128 * WSTRIDE * 2)
#define SM_TOT (SM_WLO + 128 * WSTRIDE * 2)

__global__ __launch_bounds__(256, 2)
void gemm1_mma_kernel(const float* __restrict__ X,
                      const float* __restrict__ b1,
                      int Nrows)
{
    extern __shared__ char smem[];
    uint32_t sb  = smem_u32(smem);
    int tid  = threadIdx.x;
    int wid  = tid >> 5;
    int lane = tid & 31;
    int row0 = blockIdx.x * 64;

    // --- copy pre-split W images, linear uint4 (conflict-free; 34816B each) ---
    for (int i = tid * 16; i < 128 * WSTRIDE * 2; i += 256 * 16) {
        *(uint4*)(smem + SM_WHI + i) = *(const uint4*)((const char*)g_Whi + i);
        *(uint4*)(smem + SM_WLO + i) = *(const uint4*)((const char*)g_Wlo + i);
    }

    // --- convert X tile (64 rows) fp32 -> bf16 hi/lo, padded [row][WSTRIDE].
    //     Mapping r = tid&63, q = tid>>6: each 8-lane STS phase hits banks
    //     4r (r consecutive) -> 0,4,...,28 distinct: conflict-free. ---
    {
        int r  = tid & 63;            // 0..63 row
        int q  = tid >> 6;            // 0..3  32-col quarter
        int gr = row0 + r;
        const float* xr = X + (size_t)gr * FEAT;
        #pragma unroll
        for (int j = 0; j < 4; j++) {
            int c0 = q * 32 + j * 8;
            float4 v0 = make_float4(0.f, 0.f, 0.f, 0.f), v1 = v0;
            if (gr < Nrows) {
                v0 = *(const float4*)&xr[c0];
                v1 = *(const float4*)&xr[c0 + 4];
            }
            float xs[8] = {v0.x, v0.y, v0.z, v0.w, v1.x, v1.y, v1.z, v1.w};
            unsigned hi[4], lo[4];
            #pragma unroll
            for (int p = 0; p < 4; p++) {
                float a = xs[2 * p], b = xs[2 * p + 1];
                __nv_bfloat162 h = __floats2bfloat162_rn(a, b);
                float2 hf = __bfloat1622float2(h);
                __nv_bfloat162 l = __floats2bfloat162_rn(a - hf.x, b - hf.y);
                hi[p] = *(unsigned*)&h;
                lo[p] = *(unsigned*)&l;
            }
            int off = (r * WSTRIDE + c0) * 2;
            *(uint4*)(smem + SM_XHI + off) = make_uint4(hi[0], hi[1], hi[2], hi[3]);
            *(uint4*)(smem + SM_XLO + off) = make_uint4(lo[0], lo[1], lo[2], lo[3]);
        }
    }
    __syncthreads();

    // --- fragment address bases ---
    int sub = lane >> 3, rr = lane & 7;
    int wr = (wid & 3) * 16;          // warp row base
    int wc = (wid >> 2) * 64;         // warp col base
    int a_m = wr + (sub & 1) * 8 + rr;
    int a_k = (sub >> 1) * 8;
    uint32_t aOff = (uint32_t)((a_m * WSTRIDE + a_k) * 2);
    int b_n = wc + (sub >> 1) * 8 + rr;
    int b_k = (sub & 1) * 8;
    uint32_t bOff = (uint32_t)((b_n * WSTRIDE + b_k) * 2);

    float d[8][4];
    #pragma unroll
    for (int j = 0; j < 8; j++)
        #pragma unroll
        for (int q = 0; q < 4; q++) d[j][q] = 0.f;

    #pragma unroll 1
    for (int pass = 0; pass < 3; pass++) {
        uint32_t aBase = sb + ((pass < 2)  ? SM_XHI : SM_XLO) + aOff;
        uint32_t bBase = sb + ((pass == 1) ? SM_WLO : SM_WHI) + bOff;
        #pragma unroll 4
        for (int ks = 0; ks < 8; ks++) {
            uint32_t a[4];
            LDSM4(a, aBase + (uint32_t)ks * 32);
            uint32_t bAddr = bBase + (uint32_t)ks * 32;
            #pragma unroll
            for (int np = 0; np < 4; np++) {
                uint32_t b[4];
                LDSM4(b, bAddr + (uint32_t)(np * 16 * WSTRIDE * 2));
                MMA16816(d[np * 2],     a, b[0], b[1]);
                MMA16816(d[np * 2 + 1], a, b[2], b[3]);
            }
        }
    }

    // --- epilogue: bias + tanh, store to g_T ---
    {
        int g = lane >> 2, c = lane & 3;
        int gr0 = row0 + wr + g, gr1 = gr0 + 8;
        #pragma unroll
        for (int j = 0; j < 8; j++) {
            int col = wc + j * 8 + c * 2;
            float bx = b1[col], by = b1[col + 1];
            if (gr0 < Nrows) {
                float2 o;
                o.x = tanhf(d[j][0] + bx);
                o.y = tanhf(d[j][1] + by);
                *(float2*)&g_T[(size_t)gr0 * FEAT + col] = o;
            }
            if (gr1 < Nrows) {
                float2 o;
                o.x = tanhf(d[j][2] + bx);
                o.y = tanhf(d[j][3] + by);
                *(float2*)&g_T[(size_t)gr1 * FEAT + col] = o;
            }
        }
    }
}

// ---------------------------------------------------------------------------
// Aggregate compacted edges: one warp per edge; lane handles 4 floats.
// ---------------------------------------------------------------------------
__global__ __launch_bounds__(256)
void agg_kernel()
{
    int gw   = (blockIdx.x * blockDim.x + threadIdx.x) >> 5;
    int lane = threadIdx.x & 31;
    int nw   = (gridDim.x * blockDim.x) >> 5;
    int nact = g_nact;

    for (int i = gw; i < nact; i += nw) {
        int2 e = g_ec[i];
        float4 hv = *(const float4*)&g_T[(size_t)e.y * FEAT + lane * 4];
        float* dp = &g_accT[(size_t)e.x * FEAT + lane * 4];
        asm volatile("red.global.add.v4.f32 [%0], {%1,%2,%3,%4};"
                     :: "l"(dp), "f"(hv.x), "f"(hv.y), "f"(hv.z), "f"(hv.w)
                     : "memory");
    }
}

// ---------------------------------------------------------------------------
// GEMM2 (B rows only): out[i] = flag_i * ((accT[s_i]/cnt_i) @ W2 + b2).
// ---------------------------------------------------------------------------
__global__ __launch_bounds__(256)
void gemm2_kernel(const void* __restrict__ node_idx,
                  const float* __restrict__ W2,
                  const float* __restrict__ b2,
                  float* __restrict__ out,
                  int B)
{
    extern __shared__ float sm[];
    float* sW    = sm;
    float* sA    = sm + 16384;
    float* sFlag = sm + 16384 + 8192;

    int tid  = threadIdx.x;
    int i0   = blockIdx.x * 64;
    int is64 = g_is64;

    for (int i = tid * 4; i < 16384; i += 256 * 4)
        *(float4*)&sW[i] = *(const float4*)&W2[i];

    {
        int r = tid >> 2;
        int q = tid & 3;
        int i = i0 + r;
        float  scale = 0.f;
        size_t s = 0;
        int    c = 0;
        bool   valid = (i < B);
        if (valid) {
            long long sv = is64 ? ((const long long*)node_idx)[i]
                                : (long long)((const int*)node_idx)[i];
            if ((unsigned long long)sv < (unsigned long long)N_NODES) {
                s = (size_t)sv;
                c = g_cnt[s];
            } else valid = false;
            scale = (c > 0) ? (1.f / (float)c) : 0.f;
        }
        if (q == 0) sFlag[r] = (valid && c > 0) ? 1.f : 0.f;
        #pragma unroll
        for (int j = 0; j < 8; j++) {
            int col = q * 32 + j * 4;
            float4 v = make_float4(0.f, 0.f, 0.f, 0.f);
            if (valid) {
                v = *(const float4*)&g_accT[s * FEAT + col];
                v.x *= scale; v.y *= scale; v.z *= scale; v.w *= scale;
            }
            *(float4*)&sA[r * 128 + col] = v;
        }
    }
    __syncthreads();

    int tr = tid >> 5;
    int tc = tid & 31;

    float acc[8][4];
    #pragma unroll
    for (int r = 0; r < 8; r++)
        #pragma unroll
        for (int c = 0; c < 4; c++) acc[r][c] = 0.f;

    #pragma unroll 4
    for (int k = 0; k < 128; k += 4) {
        float4 p0 = *(const float4*)&sW[(k + 0) * 128 + tc * 4];
        float4 p1 = *(const float4*)&sW[(k + 1) * 128 + tc * 4];
        float4 p2 = *(const float4*)&sW[(k + 2) * 128 + tc * 4];
        float4 p3 = *(const float4*)&sW[(k + 3) * 128 + tc * 4];
        #pragma unroll
        for (int r = 0; r < 8; r++) {
            float4 a = *(const float4*)&sA[(tr * 8 + r) * 128 + k];
            acc[r][0] += a.x * p0.x + a.y * p1.x + a.z * p2.x + a.w * p3.x;
            acc[r][1] += a.x * p0.y + a.y * p1.y + a.z * p2.y + a.w * p3.y;
            acc[r][2] += a.x * p0.z + a.y * p1.z + a.z * p2.z + a.w * p3.z;
            acc[r][3] += a.x * p0.w + a.y * p1.w + a.z * p2.w + a.w * p3.w;
        }
    }

    float4 bias = *(const float4*)&b2[tc * 4];
    #pragma unroll
    for (int r = 0; r < 8; r++) {
        int rl = tr * 8 + r;
        int i  = i0 + rl;
        if (i < B) {
            float f = sFlag[rl];
            float4 o;
            o.x = f * (acc[r][0] + bias.x);
            o.y = f * (acc[r][1] + bias.y);
            o.z = f * (acc[r][2] + bias.z);
            o.w = f * (acc[r][3] + bias.w);
            *(float4*)&out[(size_t)i * FEAT + tc * 4] = o;
        }
    }
}

// ---------------------------------------------------------------------------
extern "C" void kernel_launch(void* const* d_in, const int* in_sizes, int n_in,
                              void* d_out, int out_size)
{
    const void*  edges    = d_in[0];
    const void*  node_idx = d_in[1];
    const float* X        = (const float*)d_in[2];
    const float* W1       = (const float*)d_in[3];
    const float* b1       = (const float*)d_in[4];
    const float* W2       = (const float*)d_in[5];
    const float* b2       = (const float*)d_in[6];
    const int*   ind      = (const int*)d_in[7];

    int E = in_sizes[0] / 2;
    int B = in_sizes[1];
    int N = in_sizes[2] / FEAT;
    float* out = (float*)d_out;

    void* p_needed;
    cudaGetSymbolAddress(&p_needed, g_needed);
    cudaMemsetAsync(p_needed, 0, N_NODES);

    cudaFuncSetAttribute(gemm1_mma_kernel, cudaFuncAttributeMaxDynamicSharedMemorySize, SM_TOT);
    cudaFuncSetAttribute(gemm2_kernel,     cudaFuncAttributeMaxDynamicSharedMemorySize, 98560);

    mark_zero_kernel<<<(B * 32 + 255) / 256, 256>>>((const int*)edges, node_idx, W1, B, in_sizes[0]);
    filter_kernel<<<(E + 255) / 256, 256>>>(edges, ind, E);
    gemm1_mma_kernel<<<(N + 63) / 64, 256, SM_TOT>>>(X, b1, N);
    agg_kernel<<<1184, 256>>>();
    gemm2_kernel<<<(B + 63) / 64, 256, 98560>>>(node_idx, W2, b2, out, B);
}

// round 13
// speedup vs baseline: 1.1244x; 1.0003x over previous
#include <cuda_runtime.h>
#include <cuda_bf16.h>
#include <cstdint>
#include <cstddef>

#define N_NODES 50000
#define FEAT 128
#define E_MAX 800000
#define WSTRIDE 136   // bf16 elements per row in smem (272B = 17 * 16B -> conflict-free ldmatrix)

// ---------------- scratch (static device globals; no allocs) ----------------
// NOTE: g_needed relies on the all-zero invariant: zero-initialized at module
// load, and gemm2_kernel clears exactly the entries mark_zero set.
__device__ __align__(16) unsigned char g_needed[N_NODES];
__device__ int                         g_cnt[N_NODES];
__device__ __align__(16) float         g_accT[(size_t)N_NODES * FEAT];
__device__ __align__(16) float         g_T[(size_t)N_NODES * FEAT];
__device__ int                         g_is64;
__device__ int                         g_nact;
__device__ __align__(8)  int2          g_ec[E_MAX];                 // compacted edges
__device__ __align__(16) unsigned short g_Whi[128 * WSTRIDE];       // W1^T hi, padded [n][k]
__device__ __align__(16) unsigned short g_Wlo[128 * WSTRIDE];       // W1^T lo, padded [n][k]

__device__ __forceinline__ uint32_t smem_u32(const void* p) {
    uint32_t a;
    asm("{ .reg .u64 t; cvta.to.shared.u64 t, %1; cvt.u32.u64 %0, t; }" : "=r"(a) : "l"(p));
    return a;
}

#define LDSM4(r, addr) \
    asm volatile("ldmatrix.sync.aligned.m8n8.x4.shared.b16 {%0,%1,%2,%3}, [%4];" \
        : "=r"((r)[0]), "=r"((r)[1]), "=r"((r)[2]), "=r"((r)[3]) : "r"(addr))

#define MMA16816(d, a, b0, b1) \
    asm volatile("mma.sync.aligned.m16n8k16.row.col.f32.bf16.bf16.f32 " \
        "{%0,%1,%2,%3}, {%4,%5,%6,%7}, {%8,%9}, {%0,%1,%2,%3};" \
        : "+f"((d)[0]), "+f"((d)[1]), "+f"((d)[2]), "+f"((d)[3]) \
        : "r"((a)[0]), "r"((a)[1]), "r"((a)[2]), "r"((a)[3]), "r"(b0), "r"(b1))

#define REDV4(ptr, v) \
    asm volatile("red.global.add.v4.f32 [%0], {%1,%2,%3,%4};" \
        :: "l"(ptr), "f"((v).x), "f"((v).y), "f"((v).z), "f"((v).w) : "memory")

// ---------------------------------------------------------------------------
// mark_zero: (a) detect index dtype per-CTA and publish g_is64 / g_nact=0;
// (b) W1 split into bf16 hi/lo padded global images (first 64 CTAs);
// (c) mark needed nodes + zero their cnt and accT row (one warp per node_idx).
// ---------------------------------------------------------------------------
__global__ __launch_bounds__(256)
void mark_zero_kernel(const int* __restrict__ edges_raw,
                      const void* __restrict__ node_idx,
                      const float* __restrict__ W1,
                      int B, int E2)
{
    __shared__ int s64;
    int tid = threadIdx.x;

    // --- per-CTA dtype detect: int64 arrays of idx<2^31 have zero odd words ---
    if (tid < 32) {
        int n = E2 < 2048 ? E2 : 2048;
        int any = 0;
        for (int i = 1 + 2 * tid; i < n; i += 64) any |= edges_raw[i];
        #pragma unroll
        for (int o = 16; o; o >>= 1) any |= __shfl_xor_sync(0xffffffffu, any, o);
        if (tid == 0) s64 = (any == 0) ? 1 : 0;
    }
    __syncthreads();
    int is64 = s64;
    if (blockIdx.x == 0 && tid == 0) { g_is64 = is64; g_nact = 0; }

    // --- W split (piggy-backed; 16384 elements over first 64 CTAs) ---
    {
        int widx = blockIdx.x * 256 + tid;
        if (widx < 16384) {
            int k = widx >> 7, n = widx & 127;       // coalesced W1 read
            float w = W1[widx];
            __nv_bfloat16 hi = __float2bfloat16(w);
            __nv_bfloat16 lo = __float2bfloat16(w - __bfloat162float(hi));
            unsigned short hs, ls;
            *(__nv_bfloat16*)&hs = hi;
            *(__nv_bfloat16*)&ls = lo;
            g_Whi[n * WSTRIDE + k] = hs;
            g_Wlo[n * WSTRIDE + k] = ls;
        }
    }

    // --- mark + zero (one warp per node) ---
    int w    = (blockIdx.x * 256 + tid) >> 5;
    int lane = tid & 31;
    if (w >= B) return;
    long long s = is64 ? ((const long long*)node_idx)[w]
                       : (long long)((const int*)node_idx)[w];
    if ((unsigned long long)s >= (unsigned long long)N_NODES) return;
    if (lane == 0) { g_needed[s] = 1; g_cnt[s] = 0; }
    *(float4*)&g_accT[(size_t)s * FEAT + lane * 4] = make_float4(0.f, 0.f, 0.f, 0.f);
}

// ---------------------------------------------------------------------------
// Filter + compact edges; count degrees for needed src.
// ---------------------------------------------------------------------------
__global__ __launch_bounds__(256)
void filter_kernel(const void* __restrict__ edges, const int* __restrict__ ind_ptr, int E)
{
    int i    = blockIdx.x * blockDim.x + threadIdx.x;
    int lane = threadIdx.x & 31;
    int is64 = g_is64;
    int keep_self = (*ind_ptr < 2);

    int src = 0, dst = 0;
    bool act = false;
    if (i < E) {
        if (is64) { longlong2 p = ((const longlong2*)edges)[i]; src = (int)p.x; dst = (int)p.y; }
        else      { int2 p = ((const int2*)edges)[i];           src = p.x;      dst = p.y; }
        act = ((src != dst) | keep_self)
              && ((unsigned)src < (unsigned)N_NODES)
              && ((unsigned)dst < (unsigned)N_NODES)
              && g_needed[src];
    }
    unsigned m = __ballot_sync(0xffffffffu, act);
    int cnt = __popc(m);
    int base = 0;
    if (lane == 0 && cnt) base = atomicAdd(&g_nact, cnt);
    base = __shfl_sync(0xffffffffu, base, 0);
    if (act) {
        int off = __popc(m & ((1u << lane) - 1u));
        g_ec[base + off] = make_int2(src, dst);
        atomicAdd(&g_cnt[src], 1);
    }
}

// ---------------------------------------------------------------------------
// GEMM1 via mma.sync (HMMA bf16, 3-pass split): T = tanh(X @ W1 + b1).
// CTA: 256 threads / 8 warps; tile 64 rows x 128 cols; K=128 in smem.
// smem = 104448B -> 2 CTAs/SM. W copied linearly from pre-split global images
// (conflict-free); X-convert STS remapped for conflict-free banks.
// ---------------------------------------------------------------------------
#define SM_XHI 0
#define SM_XLO (SM_XHI + 64 * WSTRIDE * 2)
#define SM_WHI (SM_XLO + 64 * WSTRIDE * 2)
#define SM_WLO (SM_WHI + 128 * WSTRIDE * 2)
#define SM_TOT (SM_WLO + 128 * WSTRIDE * 2)

__global__ __launch_bounds__(256, 2)
void gemm1_mma_kernel(const float* __restrict__ X,
                      const float* __restrict__ b1,
                      int Nrows)
{
    extern __shared__ char smem[];
    uint32_t sb  = smem_u32(smem);
    int tid  = threadIdx.x;
    int wid  = tid >> 5;
    int lane = tid & 31;
    int row0 = blockIdx.x * 64;

    // --- copy pre-split W images, linear uint4 (conflict-free; 34816B each) ---
    for (int i = tid * 16; i < 128 * WSTRIDE * 2; i += 256 * 16) {
        *(uint4*)(smem + SM_WHI + i) = *(const uint4*)((const char*)g_Whi + i);
        *(uint4*)(smem + SM_WLO + i) = *(const uint4*)((const char*)g_Wlo + i);
    }

    // --- convert X tile (64 rows) fp32 -> bf16 hi/lo, padded [row][WSTRIDE].
    //     r = tid&63, q = tid>>6: conflict-free STS phases. ---
    {
        int r  = tid & 63;            // 0..63 row
        int q  = tid >> 6;            // 0..3  32-col quarter
        int gr = row0 + r;
        const float* xr = X + (size_t)gr * FEAT;
        #pragma unroll
        for (int j = 0; j < 4; j++) {
            int c0 = q * 32 + j * 8;
            float4 v0 = make_float4(0.f, 0.f, 0.f, 0.f), v1 = v0;
            if (gr < Nrows) {
                v0 = *(const float4*)&xr[c0];
                v1 = *(const float4*)&xr[c0 + 4];
            }
            float xs[8] = {v0.x, v0.y, v0.z, v0.w, v1.x, v1.y, v1.z, v1.w};
            unsigned hi[4], lo[4];
            #pragma unroll
            for (int p = 0; p < 4; p++) {
                float a = xs[2 * p], b = xs[2 * p + 1];
                __nv_bfloat162 h = __floats2bfloat162_rn(a, b);
                float2 hf = __bfloat1622float2(h);
                __nv_bfloat162 l = __floats2bfloat162_rn(a - hf.x, b - hf.y);
                hi[p] = *(unsigned*)&h;
                lo[p] = *(unsigned*)&l;
            }
            int off = (r * WSTRIDE + c0) * 2;
            *(uint4*)(smem + SM_XHI + off) = make_uint4(hi[0], hi[1], hi[2], hi[3]);
            *(uint4*)(smem + SM_XLO + off) = make_uint4(lo[0], lo[1], lo[2], lo[3]);
        }
    }
    __syncthreads();

    // --- fragment address bases ---
    int sub = lane >> 3, rr = lane & 7;
    int wr = (wid & 3) * 16;          // warp row base
    int wc = (wid >> 2) * 64;         // warp col base
    int a_m = wr + (sub & 1) * 8 + rr;
    int a_k = (sub >> 1) * 8;
    uint32_t aOff = (uint32_t)((a_m * WSTRIDE + a_k) * 2);
    int b_n = wc + (sub >> 1) * 8 + rr;
    int b_k = (sub & 1) * 8;
    uint32_t bOff = (uint32_t)((b_n * WSTRIDE + b_k) * 2);

    float d[8][4];
    #pragma unroll
    for (int j = 0; j < 8; j++)
        #pragma unroll
        for (int q = 0; q < 4; q++) d[j][q] = 0.f;

    #pragma unroll 1
    for (int pass = 0; pass < 3; pass++) {
        uint32_t aBase = sb + ((pass < 2)  ? SM_XHI : SM_XLO) + aOff;
        uint32_t bBase = sb + ((pass == 1) ? SM_WLO : SM_WHI) + bOff;
        #pragma unroll 4
        for (int ks = 0; ks < 8; ks++) {
            uint32_t a[4];
            LDSM4(a, aBase + (uint32_t)ks * 32);
            uint32_t bAddr = bBase + (uint32_t)ks * 32;
            #pragma unroll
            for (int np = 0; np < 4; np++) {
                uint32_t b[4];
                LDSM4(b, bAddr + (uint32_t)(np * 16 * WSTRIDE * 2));
                MMA16816(d[np * 2],     a, b[0], b[1]);
                MMA16816(d[np * 2 + 1], a, b[2], b[3]);
            }
        }
    }

    // --- epilogue: bias + tanh, store to g_T ---
    {
        int g = lane >> 2, c = lane & 3;
        int gr0 = row0 + wr + g, gr1 = gr0 + 8;
        #pragma unroll
        for (int j = 0; j < 8; j++) {
            int col = wc + j * 8 + c * 2;
            float bx = b1[col], by = b1[col + 1];
            if (gr0 < Nrows) {
                float2 o;
                o.x = tanhf(d[j][0] + bx);
                o.y = tanhf(d[j][1] + by);
                *(float2*)&g_T[(size_t)gr0 * FEAT + col] = o;
            }
            if (gr1 < Nrows) {
                float2 o;
                o.x = tanhf(d[j][2] + bx);
                o.y = tanhf(d[j][3] + by);
                *(float2*)&g_T[(size_t)gr1 * FEAT + col] = o;
            }
        }
    }
}

// ---------------------------------------------------------------------------
// Aggregate compacted edges: one warp per edge; lane handles 4 floats.
// Unroll x4 with batched loads -> MLP 4 to hide L2 latency.
// Unguarded T-row loads fall back to slot 0 (always valid); REDs are guarded.
// ---------------------------------------------------------------------------
__global__ __launch_bounds__(256)
void agg_kernel()
{
    int gw   = (blockIdx.x * blockDim.x + threadIdx.x) >> 5;
    int lane = threadIdx.x & 31;
    int nw   = (gridDim.x * blockDim.x) >> 5;
    int nact = g_nact;
    int co   = lane * 4;

    for (int i = gw; i < nact; i += 4 * nw) {
        int i1 = i + nw, i2 = i + 2 * nw, i3 = i + 3 * nw;
        int2 e0 = g_ec[i];
        int2 e1 = (i1 < nact) ? g_ec[i1] : make_int2(0, 0);
        int2 e2 = (i2 < nact) ? g_ec[i2] : make_int2(0, 0);
        int2 e3 = (i3 < nact) ? g_ec[i3] : make_int2(0, 0);

        float4 h0 = *(const float4*)&g_T[(size_t)e0.y * FEAT + co];
        float4 h1 = *(const float4*)&g_T[(size_t)e1.y * FEAT + co];
        float4 h2 = *(const float4*)&g_T[(size_t)e2.y * FEAT + co];
        float4 h3 = *(const float4*)&g_T[(size_t)e3.y * FEAT + co];

        REDV4(&g_accT[(size_t)e0.x * FEAT + co], h0);
        if (i1 < nact) REDV4(&g_accT[(size_t)e1.x * FEAT + co], h1);
        if (i2 < nact) REDV4(&g_accT[(size_t)e2.x * FEAT + co], h2);
        if (i3 < nact) REDV4(&g_accT[(size_t)e3.x * FEAT + co], h3);
    }
}

// ---------------------------------------------------------------------------
// GEMM2 (B rows only): out[i] = flag_i * ((accT[s_i]/cnt_i) @ W2 + b2).
// Also clears g_needed[s_i] to restore the all-zero invariant (no memset node).
// ---------------------------------------------------------------------------
__global__ __launch_bounds__(256)
void gemm2_kernel(const void* __restrict__ node_idx,
                  const float* __restrict__ W2,
                  const float* __restrict__ b2,
                  float* __restrict__ out,
                  int B)
{
    extern __shared__ float sm[];
    float* sW    = sm;
    float* sA    = sm + 16384;
    float* sFlag = sm + 16384 + 8192;

    int tid  = threadIdx.x;
    int i0   = blockIdx.x * 64;
    int is64 = g_is64;

    for (int i = tid * 4; i < 16384; i += 256 * 4)
        *(float4*)&sW[i] = *(const float4*)&W2[i];

    {
        int r = tid >> 2;
        int q = tid & 3;
        int i = i0 + r;
        float  scale = 0.f;
        size_t s = 0;
        int    c = 0;
        bool   valid = (i < B);
        if (valid) {
            long long sv = is64 ? ((const long long*)node_idx)[i]
                                : (long long)((const int*)node_idx)[i];
            if ((unsigned long long)sv < (unsigned long long)N_NODES) {
                s = (size_t)sv;
                c = g_cnt[s];
            } else valid = false;
            scale = (c > 0) ? (1.f / (float)c) : 0.f;
        }
        if (q == 0) {
            sFlag[r] = (valid && c > 0) ? 1.f : 0.f;
            if (valid) g_needed[s] = 0;   // restore all-zero invariant
        }
        #pragma unroll
        for (int j = 0; j < 8; j++) {
            int col = q * 32 + j * 4;
            float4 v = make_float4(0.f, 0.f, 0.f, 0.f);
            if (valid) {
                v = *(const float4*)&g_accT[s * FEAT + col];
                v.x *= scale; v.y *= scale; v.z *= scale; v.w *= scale;
            }
            *(float4*)&sA[r * 128 + col] = v;
        }
    }
    __syncthreads();

    int tr = tid >> 5;
    int tc = tid & 31;

    float acc[8][4];
    #pragma unroll
    for (int r = 0; r < 8; r++)
        #pragma unroll
        for (int c = 0; c < 4; c++) acc[r][c] = 0.f;

    #pragma unroll 4
    for (int k = 0; k < 128; k += 4) {
        float4 p0 = *(const float4*)&sW[(k + 0) * 128 + tc * 4];
        float4 p1 = *(const float4*)&sW[(k + 1) * 128 + tc * 4];
        float4 p2 = *(const float4*)&sW[(k + 2) * 128 + tc * 4];
        float4 p3 = *(const float4*)&sW[(k + 3) * 128 + tc * 4];
        #pragma unroll
        for (int r = 0; r < 8; r++) {
            float4 a = *(const float4*)&sA[(tr * 8 + r) * 128 + k];
            acc[r][0] += a.x * p0.x + a.y * p1.x + a.z * p2.x + a.w * p3.x;
            acc[r][1] += a.x * p0.y + a.y * p1.y + a.z * p2.y + a.w * p3.y;
            acc[r][2] += a.x * p0.z + a.y * p1.z + a.z * p2.z + a.w * p3.z;
            acc[r][3] += a.x * p0.w + a.y * p1.w + a.z * p2.w + a.w * p3.w;
        }
    }

    float4 bias = *(const float4*)&b2[tc * 4];
    #pragma unroll
    for (int r = 0; r < 8; r++) {
        int rl = tr * 8 + r;
        int i  = i0 + rl;
        if (i < B) {
            float f = sFlag[rl];
            float4 o;
            o.x = f * (acc[r][0] + bias.x);
            o.y = f * (acc[r][1] + bias.y);
            o.z = f * (acc[r][2] + bias.z);
            o.w = f * (acc[r][3] + bias.w);
            *(float4*)&out[(size_t)i * FEAT + tc * 4] = o;
        }
    }
}

// ---------------------------------------------------------------------------
extern "C" void kernel_launch(void* const* d_in, const int* in_sizes, int n_in,
                              void* d_out, int out_size)
{
    const void*  edges    = d_in[0];
    const void*  node_idx = d_in[1];
    const float* X        = (const float*)d_in[2];
    const float* W1       = (const float*)d_in[3];
    const float* b1       = (const float*)d_in[4];
    const float* W2       = (const float*)d_in[5];
    const float* b2       = (const float*)d_in[6];
    const int*   ind      = (const int*)d_in[7];

    int E = in_sizes[0] / 2;
    int B = in_sizes[1];
    int N = in_sizes[2] / FEAT;
    float* out = (float*)d_out;

    cudaFuncSetAttribute(gemm1_mma_kernel, cudaFuncAttributeMaxDynamicSharedMemorySize, SM_TOT);
    cudaFuncSetAttribute(gemm2_kernel,     cudaFuncAttributeMaxDynamicSharedMemorySize, 98560);

    mark_zero_kernel<<<(B * 32 + 255) / 256, 256>>>((const int*)edges, node_idx, W1, B, in_sizes[0]);
    filter_kernel<<<(E + 255) / 256, 256>>>(edges, ind, E);
    gemm1_mma_kernel<<<(N + 63) / 64, 256, SM_TOT>>>(X, b1, N);
    agg_kernel<<<1184, 256>>>();
    gemm2_kernel<<<(B + 63) / 64, 256, 98560>>>(node_idx, W2, b2, out, B);
}

// round 14
// speedup vs baseline: 1.3636x; 1.2128x over previous
#include <cuda_runtime.h>
#include <cuda_bf16.h>
#include <cstdint>
#include <cstddef>

#define N_NODES 50000
#define FEAT 128
#define WSTRIDE 136   // bf16 elements per row in smem (272B = 17 * 16B -> conflict-free ldmatrix)

// ---------------- scratch (static device globals; no allocs) ----------------
// NOTE: g_needed relies on the all-zero invariant: zero-initialized at module
// load, and gemm2_kernel clears exactly the entries mark_zero set.
__device__ __align__(16) unsigned char g_needed[N_NODES];
__device__ int                         g_cnt[N_NODES];
__device__ __align__(16) float         g_accT[(size_t)N_NODES * FEAT];
__device__ __align__(16) float         g_T[(size_t)N_NODES * FEAT];
__device__ int                         g_is64;
__device__ __align__(16) unsigned short g_Whi[128 * WSTRIDE];       // W1^T hi, padded [n][k]
__device__ __align__(16) unsigned short g_Wlo[128 * WSTRIDE];       // W1^T lo, padded [n][k]

__device__ __forceinline__ uint32_t smem_u32(const void* p) {
    uint32_t a;
    asm("{ .reg .u64 t; cvta.to.shared.u64 t, %1; cvt.u32.u64 %0, t; }" : "=r"(a) : "l"(p));
    return a;
}

#define LDSM4(r, addr) \
    asm volatile("ldmatrix.sync.aligned.m8n8.x4.shared.b16 {%0,%1,%2,%3}, [%4];" \
        : "=r"((r)[0]), "=r"((r)[1]), "=r"((r)[2]), "=r"((r)[3]) : "r"(addr))

#define MMA16816(d, a, b0, b1) \
    asm volatile("mma.sync.aligned.m16n8k16.row.col.f32.bf16.bf16.f32 " \
        "{%0,%1,%2,%3}, {%4,%5,%6,%7}, {%8,%9}, {%0,%1,%2,%3};" \
        : "+f"((d)[0]), "+f"((d)[1]), "+f"((d)[2]), "+f"((d)[3]) \
        : "r"((a)[0]), "r"((a)[1]), "r"((a)[2]), "r"((a)[3]), "r"(b0), "r"(b1))

#define REDV4(ptr, v) \
    asm volatile("red.global.add.v4.f32 [%0], {%1,%2,%3,%4};" \
        :: "l"(ptr), "f"((v).x), "f"((v).y), "f"((v).z), "f"((v).w) : "memory")

// ---------------------------------------------------------------------------
// mark_zero: (a) detect index dtype per-CTA and publish g_is64;
// (b) W1 split into bf16 hi/lo padded global images (first 64 CTAs);
// (c) mark needed nodes + zero their cnt and accT row (one warp per node_idx).
// ---------------------------------------------------------------------------
__global__ __launch_bounds__(256)
void mark_zero_kernel(const int* __restrict__ edges_raw,
                      const void* __restrict__ node_idx,
                      const float* __restrict__ W1,
                      int B, int E2)
{
    __shared__ int s64;
    int tid = threadIdx.x;

    // --- per-CTA dtype detect: int64 arrays of idx<2^31 have zero odd words ---
    if (tid < 32) {
        int n = E2 < 2048 ? E2 : 2048;
        int any = 0;
        for (int i = 1 + 2 * tid; i < n; i += 64) any |= edges_raw[i];
        #pragma unroll
        for (int o = 16; o; o >>= 1) any |= __shfl_xor_sync(0xffffffffu, any, o);
        if (tid == 0) s64 = (any == 0) ? 1 : 0;
    }
    __syncthreads();
    int is64 = s64;
    if (blockIdx.x == 0 && tid == 0) g_is64 = is64;

    // --- W split (piggy-backed; 16384 elements over first 64 CTAs) ---
    {
        int widx = blockIdx.x * 256 + tid;
        if (widx < 16384) {
            int k = widx >> 7, n = widx & 127;       // coalesced W1 read
            float w = W1[widx];
            __nv_bfloat16 hi = __float2bfloat16(w);
            __nv_bfloat16 lo = __float2bfloat16(w - __bfloat162float(hi));
            unsigned short hs, ls;
            *(__nv_bfloat16*)&hs = hi;
            *(__nv_bfloat16*)&ls = lo;
            g_Whi[n * WSTRIDE + k] = hs;
            g_Wlo[n * WSTRIDE + k] = ls;
        }
    }

    // --- mark + zero (one warp per node) ---
    int w    = (blockIdx.x * 256 + tid) >> 5;
    int lane = tid & 31;
    if (w >= B) return;
    long long s = is64 ? ((const long long*)node_idx)[w]
                       : (long long)((const int*)node_idx)[w];
    if ((unsigned long long)s >= (unsigned long long)N_NODES) return;
    if (lane == 0) { g_needed[s] = 1; g_cnt[s] = 0; }
    *(float4*)&g_accT[(size_t)s * FEAT + lane * 4] = make_float4(0.f, 0.f, 0.f, 0.f);
}

// ---------------------------------------------------------------------------
// GEMM1 via mma.sync (HMMA bf16, 3-pass split): T = tanh(X @ W1 + b1).
// CTA: 256 threads / 8 warps; tile 64 rows x 128 cols; K=128 in smem.
// smem = 104448B -> 2 CTAs/SM. W copied linearly from pre-split global images
// (conflict-free); X-convert STS remapped for conflict-free banks.
// ---------------------------------------------------------------------------
#define SM_XHI 0
#define SM_XLO (SM_XHI + 64 * WSTRIDE * 2)
#define SM_WHI (SM_XLO + 64 * WSTRIDE * 2)
#define SM_WLO (SM_WHI + 128 * WSTRIDE * 2)
#define SM_TOT (SM_WLO + 128 * WSTRIDE * 2)

__global__ __launch_bounds__(256, 2)
void gemm1_mma_kernel(const float* __restrict__ X,
                      const float* __restrict__ b1,
                      int Nrows)
{
    extern __shared__ char smem[];
    uint32_t sb  = smem_u32(smem);
    int tid  = threadIdx.x;
    int wid  = tid >> 5;
    int lane = tid & 31;
    int row0 = blockIdx.x * 64;

    // --- copy pre-split W images, linear uint4 (conflict-free; 34816B each) ---
    for (int i = tid * 16; i < 128 * WSTRIDE * 2; i += 256 * 16) {
        *(uint4*)(smem + SM_WHI + i) = *(const uint4*)((const char*)g_Whi + i);
        *(uint4*)(smem + SM_WLO + i) = *(const uint4*)((const char*)g_Wlo + i);
    }

    // --- convert X tile (64 rows) fp32 -> bf16 hi/lo, padded [row][WSTRIDE].
    //     r = tid&63, q = tid>>6: conflict-free STS phases. ---
    {
        int r  = tid & 63;            // 0..63 row
        int q  = tid >> 6;            // 0..3  32-col quarter
        int gr = row0 + r;
        const float* xr = X + (size_t)gr * FEAT;
        #pragma unroll
        for (int j = 0; j < 4; j++) {
            int c0 = q * 32 + j * 8;
            float4 v0 = make_float4(0.f, 0.f, 0.f, 0.f), v1 = v0;
            if (gr < Nrows) {
                v0 = *(const float4*)&xr[c0];
                v1 = *(const float4*)&xr[c0 + 4];
            }
            float xs[8] = {v0.x, v0.y, v0.z, v0.w, v1.x, v1.y, v1.z, v1.w};
            unsigned hi[4], lo[4];
            #pragma unroll
            for (int p = 0; p < 4; p++) {
                float a = xs[2 * p], b = xs[2 * p + 1];
                __nv_bfloat162 h = __floats2bfloat162_rn(a, b);
                float2 hf = __bfloat1622float2(h);
                __nv_bfloat162 l = __floats2bfloat162_rn(a - hf.x, b - hf.y);
                hi[p] = *(unsigned*)&h;
                lo[p] = *(unsigned*)&l;
            }
            int off = (r * WSTRIDE + c0) * 2;
            *(uint4*)(smem + SM_XHI + off) = make_uint4(hi[0], hi[1], hi[2], hi[3]);
            *(uint4*)(smem + SM_XLO + off) = make_uint4(lo[0], lo[1], lo[2], lo[3]);
        }
    }
    __syncthreads();

    // --- fragment address bases ---
    int sub = lane >> 3, rr = lane & 7;
    int wr = (wid & 3) * 16;          // warp row base
    int wc = (wid >> 2) * 64;         // warp col base
    int a_m = wr + (sub & 1) * 8 + rr;
    int a_k = (sub >> 1) * 8;
    uint32_t aOff = (uint32_t)((a_m * WSTRIDE + a_k) * 2);
    int b_n = wc + (sub >> 1) * 8 + rr;
    int b_k = (sub & 1) * 8;
    uint32_t bOff = (uint32_t)((b_n * WSTRIDE + b_k) * 2);

    float d[8][4];
    #pragma unroll
    for (int j = 0; j < 8; j++)
        #pragma unroll
        for (int q = 0; q < 4; q++) d[j][q] = 0.f;

    #pragma unroll 1
    for (int pass = 0; pass < 3; pass++) {
        uint32_t aBase = sb + ((pass < 2)  ? SM_XHI : SM_XLO) + aOff;
        uint32_t bBase = sb + ((pass == 1) ? SM_WLO : SM_WHI) + bOff;
        #pragma unroll 4
        for (int ks = 0; ks < 8; ks++) {
            uint32_t a[4];
            LDSM4(a, aBase + (uint32_t)ks * 32);
            uint32_t bAddr = bBase + (uint32_t)ks * 32;
            #pragma unroll
            for (int np = 0; np < 4; np++) {
                uint32_t b[4];
                LDSM4(b, bAddr + (uint32_t)(np * 16 * WSTRIDE * 2));
                MMA16816(d[np * 2],     a, b[0], b[1]);
                MMA16816(d[np * 2 + 1], a, b[2], b[3]);
            }
        }
    }

    // --- epilogue: bias + tanh, store to g_T ---
    {
        int g = lane >> 2, c = lane & 3;
        int gr0 = row0 + wr + g, gr1 = gr0 + 8;
        #pragma unroll
        for (int j = 0; j < 8; j++) {
            int col = wc + j * 8 + c * 2;
            float bx = b1[col], by = b1[col + 1];
            if (gr0 < Nrows) {
                float2 o;
                o.x = tanhf(d[j][0] + bx);
                o.y = tanhf(d[j][1] + by);
                *(float2*)&g_T[(size_t)gr0 * FEAT + col] = o;
            }
            if (gr1 < Nrows) {
                float2 o;
                o.x = tanhf(d[j][2] + bx);
                o.y = tanhf(d[j][3] + by);
                *(float2*)&g_T[(size_t)gr1 * FEAT + col] = o;
            }
        }
    }
}

// ---------------------------------------------------------------------------
// Fused edge filter + aggregation: single pass over edges.
// Warp owns 32 consecutive edges: coalesced decode, ballot on active,
// then serialize active lanes with whole-warp cooperative gather + RED.
// (REDs are fire-and-forget; successive gathers are independent -> natural MLP.)
// ---------------------------------------------------------------------------
__global__ __launch_bounds__(256)
void edge_kernel(const void* __restrict__ edges,
                 const int* __restrict__ ind_ptr,
                 int E)
{
    int gtid = blockIdx.x * blockDim.x + threadIdx.x;
    int lane = threadIdx.x & 31;
    int e    = gtid;                       // one edge per thread (single pass)
    int is64 = g_is64;
    int keep_self = (*ind_ptr < 2);
    int co = lane * 4;

    int src = 0, dst = 0;
    bool act = false;
    if (e < E) {
        if (is64) { longlong2 p = ((const longlong2*)edges)[e]; src = (int)p.x; dst = (int)p.y; }
        else      { int2 p = ((const int2*)edges)[e];           src = p.x;      dst = p.y; }
        act = ((src != dst) | keep_self)
              && ((unsigned)src < (unsigned)N_NODES)
              && ((unsigned)dst < (unsigned)N_NODES)
              && g_needed[src];
    }
    unsigned m = __ballot_sync(0xffffffffu, act);
    if (act) atomicAdd(&g_cnt[src], 1);
    while (m) {
        int l = __ffs(m) - 1;
        m &= m - 1;
        int s = __shfl_sync(0xffffffffu, src, l);
        int d = __shfl_sync(0xffffffffu, dst, l);
        float4 hv = *(const float4*)&g_T[(size_t)d * FEAT + co];
        REDV4(&g_accT[(size_t)s * FEAT + co], hv);
    }
}

// ---------------------------------------------------------------------------
// GEMM2 (B rows only): out[i] = flag_i * ((accT[s_i]/cnt_i) @ W2 + b2).
// Also clears g_needed[s_i] to restore the all-zero invariant (no memset node).
// ---------------------------------------------------------------------------
__global__ __launch_bounds__(256)
void gemm2_kernel(const void* __restrict__ node_idx,
                  const float* __restrict__ W2,
                  const float* __restrict__ b2,
                  float* __restrict__ out,
                  int B)
{
    extern __shared__ float sm[];
    float* sW    = sm;
    float* sA    = sm + 16384;
    float* sFlag = sm + 16384 + 8192;

    int tid  = threadIdx.x;
    int i0   = blockIdx.x * 64;
    int is64 = g_is64;

    for (int i = tid * 4; i < 16384; i += 256 * 4)
        *(float4*)&sW[i] = *(const float4*)&W2[i];

    {
        int r = tid >> 2;
        int q = tid & 3;
        int i = i0 + r;
        float  scale = 0.f;
        size_t s = 0;
        int    c = 0;
        bool   valid = (i < B);
        if (valid) {
            long long sv = is64 ? ((const long long*)node_idx)[i]
                                : (long long)((const int*)node_idx)[i];
            if ((unsigned long long)sv < (unsigned long long)N_NODES) {
                s = (size_t)sv;
                c = g_cnt[s];
            } else valid = false;
            scale = (c > 0) ? (1.f / (float)c) : 0.f;
        }
        if (q == 0) {
            sFlag[r] = (valid && c > 0) ? 1.f : 0.f;
            if (valid) g_needed[s] = 0;   // restore all-zero invariant
        }
        #pragma unroll
        for (int j = 0; j < 8; j++) {
            int col = q * 32 + j * 4;
            float4 v = make_float4(0.f, 0.f, 0.f, 0.f);
            if (valid) {
                v = *(const float4*)&g_accT[s * FEAT + col];
                v.x *= scale; v.y *= scale; v.z *= scale; v.w *= scale;
            }
            *(float4*)&sA[r * 128 + col] = v;
        }
    }
    __syncthreads();

    int tr = tid >> 5;
    int tc = tid & 31;

    float acc[8][4];
    #pragma unroll
    for (int r = 0; r < 8; r++)
        #pragma unroll
        for (int c = 0; c < 4; c++) acc[r][c] = 0.f;

    #pragma unroll 4
    for (int k = 0; k < 128; k += 4) {
        float4 p0 = *(const float4*)&sW[(k + 0) * 128 + tc * 4];
        float4 p1 = *(const float4*)&sW[(k + 1) * 128 + tc * 4];
        float4 p2 = *(const float4*)&sW[(k + 2) * 128 + tc * 4];
        float4 p3 = *(const float4*)&sW[(k + 3) * 128 + tc * 4];
        #pragma unroll
        for (int r = 0; r < 8; r++) {
            float4 a = *(const float4*)&sA[(tr * 8 + r) * 128 + k];
            acc[r][0] += a.x * p0.x + a.y * p1.x + a.z * p2.x + a.w * p3.x;
            acc[r][1] += a.x * p0.y + a.y * p1.y + a.z * p2.y + a.w * p3.y;
            acc[r][2] += a.x * p0.z + a.y * p1.z + a.z * p2.z + a.w * p3.z;
            acc[r][3] += a.x * p0.w + a.y * p1.w + a.z * p2.w + a.w * p3.w;
        }
    }

    float4 bias = *(const float4*)&b2[tc * 4];
    #pragma unroll
    for (int r = 0; r < 8; r++) {
        int rl = tr * 8 + r;
        int i  = i0 + rl;
        if (i < B) {
            float f = sFlag[rl];
            float4 o;
            o.x = f * (acc[r][0] + bias.x);
            o.y = f * (acc[r][1] + bias.y);
            o.z = f * (acc[r][2] + bias.z);
            o.w = f * (acc[r][3] + bias.w);
            *(float4*)&out[(size_t)i * FEAT + tc * 4] = o;
        }
    }
}

// ---------------------------------------------------------------------------
extern "C" void kernel_launch(void* const* d_in, const int* in_sizes, int n_in,
                              void* d_out, int out_size)
{
    const void*  edges    = d_in[0];
    const void*  node_idx = d_in[1];
    const float* X        = (const float*)d_in[2];
    const float* W1       = (const float*)d_in[3];
    const float* b1       = (const float*)d_in[4];
    const float* W2       = (const float*)d_in[5];
    const float* b2       = (const float*)d_in[6];
    const int*   ind      = (const int*)d_in[7];

    int E = in_sizes[0] / 2;
    int B = in_sizes[1];
    int N = in_sizes[2] / FEAT;
    float* out = (float*)d_out;

    cudaFuncSetAttribute(gemm1_mma_kernel, cudaFuncAttributeMaxDynamicSharedMemorySize, SM_TOT);
    cudaFuncSetAttribute(gemm2_kernel,     cudaFuncAttributeMaxDynamicSharedMemorySize, 98560);

    mark_zero_kernel<<<(B * 32 + 255) / 256, 256>>>((const int*)edges, node_idx, W1, B, in_sizes[0]);
    gemm1_mma_kernel<<<(N + 63) / 64, 256, SM_TOT>>>(X, b1, N);
    edge_kernel<<<(E + 255) / 256, 256>>>(edges, ind, E);
    gemm2_kernel<<<(B + 63) / 64, 256, 98560>>>(node_idx, W2, b2, out, B);
}

// round 15
// speedup vs baseline: 1.5385x; 1.1282x over previous
#include <cuda_runtime.h>
#include <cuda_bf16.h>
#include <cstdint>
#include <cstddef>

#define N_NODES 50000
#define FEAT 128
#define WSTRIDE 136   // bf16 elements per row in smem (272B = 17 * 16B -> conflict-free ldmatrix)

// ---------------- scratch (static device globals; no allocs) ----------------
// NOTE: g_needed relies on the all-zero invariant: zero-initialized at module
// load, and gemm2 clears exactly the entries mark_zero set.
__device__ __align__(16) unsigned char g_needed[N_NODES];
__device__ int                         g_cnt[N_NODES];
__device__ __align__(16) float         g_accT[(size_t)N_NODES * FEAT];
__device__ __align__(16) float         g_T[(size_t)N_NODES * FEAT];
__device__ int                         g_is64;
__device__ __align__(16) unsigned short g_Whi[128 * WSTRIDE];        // W1^T hi, padded [n][k]
__device__ __align__(16) unsigned short g_Wlo[128 * WSTRIDE];        // W1^T lo, padded [n][k]
__device__ __align__(16) unsigned short g_W2hi[128 * WSTRIDE];       // W2^T hi
__device__ __align__(16) unsigned short g_W2lo[128 * WSTRIDE];       // W2^T lo

__device__ __forceinline__ uint32_t smem_u32(const void* p) {
    uint32_t a;
    asm("{ .reg .u64 t; cvta.to.shared.u64 t, %1; cvt.u32.u64 %0, t; }" : "=r"(a) : "l"(p));
    return a;
}

#define LDSM4(r, addr) \
    asm volatile("ldmatrix.sync.aligned.m8n8.x4.shared.b16 {%0,%1,%2,%3}, [%4];" \
        : "=r"((r)[0]), "=r"((r)[1]), "=r"((r)[2]), "=r"((r)[3]) : "r"(addr))

#define MMA16816(d, a, b0, b1) \
    asm volatile("mma.sync.aligned.m16n8k16.row.col.f32.bf16.bf16.f32 " \
        "{%0,%1,%2,%3}, {%4,%5,%6,%7}, {%8,%9}, {%0,%1,%2,%3};" \
        : "+f"((d)[0]), "+f"((d)[1]), "+f"((d)[2]), "+f"((d)[3]) \
        : "r"((a)[0]), "r"((a)[1]), "r"((a)[2]), "r"((a)[3]), "r"(b0), "r"(b1))

#define REDV4(ptr, v) \
    asm volatile("red.global.add.v4.f32 [%0], {%1,%2,%3,%4};" \
        :: "l"(ptr), "f"((v).x), "f"((v).y), "f"((v).z), "f"((v).w) : "memory")

// ---------------------------------------------------------------------------
// mark_zero: (a) detect index dtype per-CTA and publish g_is64;
// (b) W1+W2 split into bf16 hi/lo padded global images (first 128 CTAs);
// (c) mark needed nodes + zero their cnt and accT row (one warp per node_idx).
// ---------------------------------------------------------------------------
__global__ __launch_bounds__(256)
void mark_zero_kernel(const int* __restrict__ edges_raw,
                      const void* __restrict__ node_idx,
                      const float* __restrict__ W1,
                      const float* __restrict__ W2,
                      int B, int E2)
{
    __shared__ int s64;
    int tid = threadIdx.x;

    // --- per-CTA dtype detect: int64 arrays of idx<2^31 have zero odd words ---
    if (tid < 32) {
        int n = E2 < 2048 ? E2 : 2048;
        int any = 0;
        for (int i = 1 + 2 * tid; i < n; i += 64) any |= edges_raw[i];
        #pragma unroll
        for (int o = 16; o; o >>= 1) any |= __shfl_xor_sync(0xffffffffu, any, o);
        if (tid == 0) s64 = (any == 0) ? 1 : 0;
    }
    __syncthreads();
    int is64 = s64;
    if (blockIdx.x == 0 && tid == 0) g_is64 = is64;

    // --- W split (piggy-backed; 2*16384 elements over first 128 CTAs) ---
    {
        int widx = blockIdx.x * 256 + tid;
        if (widx < 32768) {
            const float* Wsrc = (widx < 16384) ? W1 : W2;
            int lidx = widx & 16383;
            int k = lidx >> 7, n = lidx & 127;       // coalesced read
            float w = Wsrc[lidx];
            __nv_bfloat16 hi = __float2bfloat16(w);
            __nv_bfloat16 lo = __float2bfloat16(w - __bfloat162float(hi));
            unsigned short hs, ls;
            *(__nv_bfloat16*)&hs = hi;
            *(__nv_bfloat16*)&ls = lo;
            if (widx < 16384) { g_Whi[n * WSTRIDE + k]  = hs; g_Wlo[n * WSTRIDE + k]  = ls; }
            else              { g_W2hi[n * WSTRIDE + k] = hs; g_W2lo[n * WSTRIDE + k] = ls; }
        }
    }

    // --- mark + zero (one warp per node) ---
    int w    = (blockIdx.x * 256 + tid) >> 5;
    int lane = tid & 31;
    if (w >= B) return;
    long long s = is64 ? ((const long long*)node_idx)[w]
                       : (long long)((const int*)node_idx)[w];
    if ((unsigned long long)s >= (unsigned long long)N_NODES) return;
    if (lane == 0) { g_needed[s] = 1; g_cnt[s] = 0; }
    *(float4*)&g_accT[(size_t)s * FEAT + lane * 4] = make_float4(0.f, 0.f, 0.f, 0.f);
}

// ---------------------------------------------------------------------------
// Shared smem layout for both MMA GEMMs (64-row tiles, 2 CTAs/SM).
// ---------------------------------------------------------------------------
#define SM_XHI  0
#define SM_XLO  (SM_XHI + 64 * WSTRIDE * 2)
#define SM_WHI  (SM_XLO + 64 * WSTRIDE * 2)
#define SM_WLO  (SM_WHI + 128 * WSTRIDE * 2)
#define SM_FLAG (SM_WLO + 128 * WSTRIDE * 2)
#define SM_TOT  (SM_FLAG + 256)

// Shared HMMA 3-pass mainloop over smem images. Returns d[8][4] per warp.
__device__ __forceinline__ void mma_mainloop(uint32_t sb, int wid, int lane,
                                             float d[8][4])
{
    int sub = lane >> 3, rr = lane & 7;
    int wr = (wid & 3) * 16;
    int wc = (wid >> 2) * 64;
    int a_m = wr + (sub & 1) * 8 + rr;
    int a_k = (sub >> 1) * 8;
    uint32_t aOff = (uint32_t)((a_m * WSTRIDE + a_k) * 2);
    int b_n = wc + (sub >> 1) * 8 + rr;
    int b_k = (sub & 1) * 8;
    uint32_t bOff = (uint32_t)((b_n * WSTRIDE + b_k) * 2);

    #pragma unroll
    for (int j = 0; j < 8; j++)
        #pragma unroll
        for (int q = 0; q < 4; q++) d[j][q] = 0.f;

    #pragma unroll 1
    for (int pass = 0; pass < 3; pass++) {
        uint32_t aBase = sb + ((pass < 2)  ? SM_XHI : SM_XLO) + aOff;
        uint32_t bBase = sb + ((pass == 1) ? SM_WLO : SM_WHI) + bOff;
        #pragma unroll 4
        for (int ks = 0; ks < 8; ks++) {
            uint32_t a[4];
            LDSM4(a, aBase + (uint32_t)ks * 32);
            uint32_t bAddr = bBase + (uint32_t)ks * 32;
            #pragma unroll
            for (int np = 0; np < 4; np++) {
                uint32_t b[4];
                LDSM4(b, bAddr + (uint32_t)(np * 16 * WSTRIDE * 2));
                MMA16816(d[np * 2],     a, b[0], b[1]);
                MMA16816(d[np * 2 + 1], a, b[2], b[3]);
            }
        }
    }
}

// Convert 8 contiguous floats -> hi/lo bf16x2 quads and store to smem row.
__device__ __forceinline__ void split_store(char* smem, int r, int c0,
                                            float4 v0, float4 v1)
{
    float xs[8] = {v0.x, v0.y, v0.z, v0.w, v1.x, v1.y, v1.z, v1.w};
    unsigned hi[4], lo[4];
    #pragma unroll
    for (int p = 0; p < 4; p++) {
        float a = xs[2 * p], b = xs[2 * p + 1];
        __nv_bfloat162 h = __floats2bfloat162_rn(a, b);
        float2 hf = __bfloat1622float2(h);
        __nv_bfloat162 l = __floats2bfloat162_rn(a - hf.x, b - hf.y);
        hi[p] = *(unsigned*)&h;
        lo[p] = *(unsigned*)&l;
    }
    int off = (r * WSTRIDE + c0) * 2;
    *(uint4*)(smem + SM_XHI + off) = make_uint4(hi[0], hi[1], hi[2], hi[3]);
    *(uint4*)(smem + SM_XLO + off) = make_uint4(lo[0], lo[1], lo[2], lo[3]);
}

// ---------------------------------------------------------------------------
// GEMM1 via mma.sync (HMMA bf16, 3-pass split): T = tanh(X @ W1 + b1).
// ---------------------------------------------------------------------------
__global__ __launch_bounds__(256, 2)
void gemm1_mma_kernel(const float* __restrict__ X,
                      const float* __restrict__ b1,
                      int Nrows)
{
    extern __shared__ char smem[];
    uint32_t sb  = smem_u32(smem);
    int tid  = threadIdx.x;
    int wid  = tid >> 5;
    int lane = tid & 31;
    int row0 = blockIdx.x * 64;

    for (int i = tid * 16; i < 128 * WSTRIDE * 2; i += 256 * 16) {
        *(uint4*)(smem + SM_WHI + i) = *(const uint4*)((const char*)g_Whi + i);
        *(uint4*)(smem + SM_WLO + i) = *(const uint4*)((const char*)g_Wlo + i);
    }

    {
        int r  = tid & 63;
        int q  = tid >> 6;
        int gr = row0 + r;
        const float* xr = X + (size_t)gr * FEAT;
        #pragma unroll
        for (int j = 0; j < 4; j++) {
            int c0 = q * 32 + j * 8;
            float4 v0 = make_float4(0.f, 0.f, 0.f, 0.f), v1 = v0;
            if (gr < Nrows) {
                v0 = *(const float4*)&xr[c0];
                v1 = *(const float4*)&xr[c0 + 4];
            }
            split_store(smem, r, c0, v0, v1);
        }
    }
    __syncthreads();

    float d[8][4];
    mma_mainloop(sb, wid, lane, d);

    {
        int g = lane >> 2, c = lane & 3;
        int wr = (wid & 3) * 16, wc = (wid >> 2) * 64;
        int gr0 = row0 + wr + g, gr1 = gr0 + 8;
        #pragma unroll
        for (int j = 0; j < 8; j++) {
            int col = wc + j * 8 + c * 2;
            float bx = b1[col], by = b1[col + 1];
            if (gr0 < Nrows) {
                float2 o;
                o.x = tanhf(d[j][0] + bx);
                o.y = tanhf(d[j][1] + by);
                *(float2*)&g_T[(size_t)gr0 * FEAT + col] = o;
            }
            if (gr1 < Nrows) {
                float2 o;
                o.x = tanhf(d[j][2] + bx);
                o.y = tanhf(d[j][3] + by);
                *(float2*)&g_T[(size_t)gr1 * FEAT + col] = o;
            }
        }
    }
}

// ---------------------------------------------------------------------------
// Fused edge filter + aggregation: single pass over edges (R14-verified).
// ---------------------------------------------------------------------------
__global__ __launch_bounds__(256)
void edge_kernel(const void* __restrict__ edges,
                 const int* __restrict__ ind_ptr,
                 int E)
{
    int gtid = blockIdx.x * blockDim.x + threadIdx.x;
    int lane = threadIdx.x & 31;
    int e    = gtid;
    int is64 = g_is64;
    int keep_self = (*ind_ptr < 2);
    int co = lane * 4;

    int src = 0, dst = 0;
    bool act = false;
    if (e < E) {
        if (is64) { longlong2 p = ((const longlong2*)edges)[e]; src = (int)p.x; dst = (int)p.y; }
        else      { int2 p = ((const int2*)edges)[e];           src = p.x;      dst = p.y; }
        act = ((src != dst) | keep_self)
              && ((unsigned)src < (unsigned)N_NODES)
              && ((unsigned)dst < (unsigned)N_NODES)
              && g_needed[src];
    }
    unsigned m = __ballot_sync(0xffffffffu, act);
    if (act) atomicAdd(&g_cnt[src], 1);
    while (m) {
        int l = __ffs(m) - 1;
        m &= m - 1;
        int s = __shfl_sync(0xffffffffu, src, l);
        int d = __shfl_sync(0xffffffffu, dst, l);
        float4 hv = *(const float4*)&g_T[(size_t)d * FEAT + co];
        REDV4(&g_accT[(size_t)s * FEAT + co], hv);
    }
}

// ---------------------------------------------------------------------------
// GEMM2 via mma.sync (HMMA bf16, 3-pass split):
// out[i] = flag_i * ((accT[s_i]/cnt_i) @ W2 + b2); clears g_needed[s_i].
// ---------------------------------------------------------------------------
__global__ __launch_bounds__(256, 2)
void gemm2_mma_kernel(const void* __restrict__ node_idx,
                      const float* __restrict__ b2,
                      float* __restrict__ out,
                      int B)
{
    extern __shared__ char smem[];
    uint32_t sb  = smem_u32(smem);
    float* sFlag = (float*)(smem + SM_FLAG);
    int tid  = threadIdx.x;
    int wid  = tid >> 5;
    int lane = tid & 31;
    int i0   = blockIdx.x * 64;
    int is64 = g_is64;

    for (int i = tid * 16; i < 128 * WSTRIDE * 2; i += 256 * 16) {
        *(uint4*)(smem + SM_WHI + i) = *(const uint4*)((const char*)g_W2hi + i);
        *(uint4*)(smem + SM_WLO + i) = *(const uint4*)((const char*)g_W2lo + i);
    }

    // --- gather + scale + split A = accT[node_idx[i]] / cnt ---
    {
        int r = tid & 63;
        int q = tid >> 6;
        int i = i0 + r;
        float  scale = 0.f;
        size_t s = 0;
        int    c = 0;
        bool   valid = (i < B);
        if (valid) {
            long long sv = is64 ? ((const long long*)node_idx)[i]
                                : (long long)((const int*)node_idx)[i];
            if ((unsigned long long)sv < (unsigned long long)N_NODES) {
                s = (size_t)sv;
                c = g_cnt[s];
            } else valid = false;
            scale = (c > 0) ? (1.f / (float)c) : 0.f;
        }
        if (q == 0) {
            sFlag[r] = (valid && c > 0) ? 1.f : 0.f;
            if (valid) g_needed[s] = 0;   // restore all-zero invariant
        }
        const float* ar = &g_accT[s * FEAT];
        #pragma unroll
        for (int j = 0; j < 4; j++) {
            int c0 = q * 32 + j * 8;
            float4 v0 = make_float4(0.f, 0.f, 0.f, 0.f), v1 = v0;
            if (valid) {
                v0 = *(const float4*)&ar[c0];
                v1 = *(const float4*)&ar[c0 + 4];
                v0.x *= scale; v0.y *= scale; v0.z *= scale; v0.w *= scale;
                v1.x *= scale; v1.y *= scale; v1.z *= scale; v1.w *= scale;
            }
            split_store(smem, r, c0, v0, v1);
        }
    }
    __syncthreads();

    float d[8][4];
    mma_mainloop(sb, wid, lane, d);

    {
        int g = lane >> 2, c = lane & 3;
        int wr = (wid & 3) * 16, wc = (wid >> 2) * 64;
        int r0 = wr + g, r1 = r0 + 8;
        int i0r0 = i0 + r0, i0r1 = i0 + r1;
        float f0 = sFlag[r0], f1 = sFlag[r1];
        #pragma unroll
        for (int j = 0; j < 8; j++) {
            int col = wc + j * 8 + c * 2;
            float bx = b2[col], by = b2[col + 1];
            if (i0r0 < B) {
                float2 o;
                o.x = f0 * (d[j][0] + bx);
                o.y = f0 * (d[j][1] + by);
                *(float2*)&out[(size_t)i0r0 * FEAT + col] = o;
            }
            if (i0r1 < B) {
                float2 o;
                o.x = f1 * (d[j][2] + bx);
                o.y = f1 * (d[j][3] + by);
                *(float2*)&out[(size_t)i0r1 * FEAT + col] = o;
            }
        }
    }
}

// ---------------------------------------------------------------------------
extern "C" void kernel_launch(void* const* d_in, const int* in_sizes, int n_in,
                              void* d_out, int out_size)
{
    const void*  edges    = d_in[0];
    const void*  node_idx = d_in[1];
    const float* X        = (const float*)d_in[2];
    const float* W1       = (const float*)d_in[3];
    const float* b1       = (const float*)d_in[4];
    const float* W2       = (const float*)d_in[5];
    const float* b2       = (const float*)d_in[6];
    const int*   ind      = (const int*)d_in[7];

    int E = in_sizes[0] / 2;
    int B = in_sizes[1];
    int N = in_sizes[2] / FEAT;
    float* out = (float*)d_out;

    cudaFuncSetAttribute(gemm1_mma_kernel, cudaFuncAttributeMaxDynamicSharedMemorySize, SM_TOT);
    cudaFuncSetAttribute(gemm2_mma_kernel, cudaFuncAttributeMaxDynamicSharedMemorySize, SM_TOT);

    mark_zero_kernel<<<(B * 32 + 255) / 256, 256>>>((const int*)edges, node_idx, W1, W2, B, in_sizes[0]);
    gemm1_mma_kernel<<<(N + 63) / 64, 256, SM_TOT>>>(X, b1, N);
    edge_kernel<<<(E + 255) / 256, 256>>>(edges, ind, E);
    gemm2_mma_kernel<<<(B + 63) / 64, 256, SM_TOT>>>(node_idx, b2, out, B);
}